// round 15
// baseline (speedup 1.0000x reference)
#include <cuda_runtime.h>
#include <stdint.h>

#define BATCH 2
#define NBOX 16384
#define PRE 1024
#define POST 512
#define NMSW 16            // 1024 bits / 64
#define NMS_THRESH 0.8f
#define CAND_CAP 2048
#define NCELLX 13
#define NCELL (NCELLX * NCELLX)
#define CELL_CAP 64
#define HBITS 14
#define HBINS (1 << HBITS)
#define TPB 1024

typedef unsigned long long u64;

struct __align__(16) Box5 { float x, y, dx, dy, c, s, rad, area; };

__device__ int      g_topidx[BATCH][PRE];
__device__ Box5     g_box[BATCH][PRE];
__device__ float    g_cor[BATCH][PRE][8];
__device__ float4   g_f4[BATCH][PRE];           // x, y, rad, area (by rank)
__device__ u64      g_suppby[BATCH][PRE][NMSW]; // supp_by[j]: bits i<j with iou>th
__device__ u64      g_rowflag[BATCH][NMSW];
__device__ u64      g_keys[BATCH][NBOX];
__device__ unsigned g_hist[BATCH][HBINS];       // zeroed in pairheavy (cyclic)
__device__ int      g_ccount[BATCH];
__device__ u64      g_cand[BATCH][CAND_CAP];
__device__ unsigned g_cellcnt[BATCH][NCELL];
__device__ int      g_cellboxes[BATCH][NCELL][CELL_CAP];  // direct-mapped cell slabs

__device__ __forceinline__ int cell_of(float v) {
    int c = (int)floorf((v + 50.0f) * 0.125f);
    return c < 0 ? 0 : (c > NCELLX - 1 ? NCELLX - 1 : c);
}

// ==========================================================================
// 1) keys + 14-bit-prefix histogram; zeroes all per-replay flags.
//    grid = 128 x 256 = exactly BATCH*NBOX threads.
// ==========================================================================
__global__ void key_kernel(const float* __restrict__ cls) {
    int t = blockIdx.x * blockDim.x + threadIdx.x;
    ((u64*)g_suppby)[t] = 0ull;                  // BATCH*PRE*NMSW == 32768 == #threads
    if (t < BATCH * NMSW) ((u64*)g_rowflag)[t] = 0ull;
    if (t < BATCH) g_ccount[t] = 0;
    if (t < BATCH * NCELL) ((unsigned*)g_cellcnt)[t] = 0u;

    int b = t >> 14, i = t & (NBOX - 1);
    const float* p = cls + ((long)t) * 3;
    float sc = fmaxf(p[0], fmaxf(p[1], p[2]));
    unsigned u = __float_as_uint(sc);
    unsigned m = (u & 0x80000000u) ? ~u : (u | 0x80000000u); // ascending monotone
    u64 k = (((u64)(~m)) << 32) | (unsigned)i;  // u64 asc == score desc, idx asc
    g_keys[b][i] = k;
    atomicAdd(&g_hist[b][(unsigned)(k >> (64 - HBITS))], 1u);
}

// ==========================================================================
// 2) compact: per-CTA redundant threshold scan, then compact 256-key slice.
//    grid = 128 x 256.
// ==========================================================================
__global__ void __launch_bounds__(256) compact_kernel() {
    __shared__ unsigned warpsum[8];
    __shared__ unsigned sT;
    int tid = threadIdx.x;
    int t = blockIdx.x * blockDim.x + tid;
    int b = t >> 14, i = t & (NBOX - 1);
    int lane = tid & 31, wid = tid >> 5;

    const unsigned* h = g_hist[b];
    unsigned psum = 0;
    {
        const uint4* h4 = (const uint4*)(h + tid * (HBINS / 256));
#pragma unroll
        for (int k = 0; k < HBINS / 256 / 4; k++) {   // 16 uint4 = 64 bins
            uint4 v = h4[k];
            psum += v.x + v.y + v.z + v.w;
        }
    }
    unsigned sc = psum;
#pragma unroll
    for (int off = 1; off < 32; off <<= 1) {
        unsigned v = __shfl_up_sync(0xffffffffu, sc, off);
        if (lane >= off) sc += v;
    }
    if (lane == 31) warpsum[wid] = sc;
    __syncthreads();
    unsigned woff = 0;
#pragma unroll
    for (int w = 0; w < 8; w++) woff += (w < wid) ? warpsum[w] : 0u;
    unsigned incl = sc + woff;
    unsigned excl = incl - psum;
    if (incl >= PRE && excl < PRE) {
        unsigned c = excl;
        int base = tid * (HBINS / 256);
        for (int k = 0; k < HBINS / 256; k++) {
            c += h[base + k];
            if (c >= PRE) { sT = (unsigned)(base + k); break; }
        }
    }
    __syncthreads();
    unsigned T = sT;

    u64 k = g_keys[b][i];
    if ((unsigned)(k >> (64 - HBITS)) <= T) {
        int pos = atomicAdd(&g_ccount[b], 1);
        if (pos < CAND_CAP) g_cand[b][pos] = k;
    }
}

// ==========================================================================
// 3) rank: stable sorted position = #{keys < mine} (keys unique).
//    Threads with rank < PRE do box prep + direct cell-slab registration.
//    grid = 16 x 256 = BATCH * CAND_CAP threads.
// ==========================================================================
__global__ void __launch_bounds__(256) rank_kernel(const float* __restrict__ boxes) {
    int t = blockIdx.x * blockDim.x + threadIdx.x;
    int b = t / CAND_CAP;
    int c = t - b * CAND_CAP;
    int m = g_ccount[b]; if (m > CAND_CAP) m = CAND_CAP;
    if (c >= m) return;

    const u64* cand = g_cand[b];
    u64 mykey = cand[c];

    int rank = 0;
    int j = 0;
    for (; j + 2 <= m; j += 2) {
        ulonglong2 v = *(const ulonglong2*)(cand + j);
        rank += (v.x < mykey) + (v.y < mykey);
    }
    for (; j < m; j++) rank += (cand[j] < mykey);
    if (rank >= PRE) return;

    int idx = (int)(mykey & 0xFFFFFFFFull);
    g_topidx[b][rank] = idx;
    const float* bp = boxes + ((long)b * NBOX + idx) * 7;
    float x = bp[0], y = bp[1], dx = bp[3], dy = bp[4], r = bp[6];
    float cc = cosf(r), ss = sinf(r);
    Box5 bx;
    bx.x = x; bx.y = y; bx.dx = dx; bx.dy = dy; bx.c = cc; bx.s = ss;
    bx.rad = 0.5f * sqrtf(dx * dx + dy * dy);
    bx.area = dx * dy;
    g_box[b][rank] = bx;
    g_f4[b][rank] = make_float4(x, y, bx.rad, bx.area);
    const float ox[4] = {0.5f, -0.5f, -0.5f, 0.5f};
    const float oy[4] = {0.5f, 0.5f, -0.5f, -0.5f};
    float* co = g_cor[b][rank];
#pragma unroll
    for (int k = 0; k < 4; k++) {
        float lx = dx * ox[k], ly = dy * oy[k];
        co[2 * k]     = x + lx * cc - ly * ss;
        co[2 * k + 1] = y + lx * ss + ly * cc;
    }
    int cell = cell_of(y) * NCELLX + cell_of(x);
    unsigned slot = atomicAdd(&g_cellcnt[b][cell], 1u);
    if (slot < CELL_CAP) g_cellboxes[b][cell][slot] = rank;
}

// ==========================================================================
// Warp-parallel reference-faithful rotated BEV IoU.
// __noinline__: keeps ptxas register allocation tractable inside the
// pairheavy dispatch loop (R14 force-inline version failed to compile).
// ==========================================================================
__device__ __noinline__ float warp_rotated_iou(int b, int i, int j, int lane) {
    const unsigned FULL = 0xffffffffu;
    Box5 A  = g_box[b][i];
    Box5 Bx = g_box[b][j];
    const float* CA = g_cor[b][i];
    const float* CB = g_cor[b][j];

    float px = 0.0f, py = 0.0f;
    bool ok = false;
    if (lane < 16) {
        int p = lane >> 2, q = lane & 3;
        int p1 = (p + 1) & 3, q1 = (q + 1) & 3;
        float ax = CA[2 * p],  ay = CA[2 * p + 1];
        float dax = CA[2 * p1] - ax, day = CA[2 * p1 + 1] - ay;
        float bx = CB[2 * q],  by = CB[2 * q + 1];
        float dbx = CB[2 * q1] - bx, dby = CB[2 * q1 + 1] - by;
        float den = dax * dby - day * dbx;
        float ddx = bx - ax, ddy = by - ay;
        bool denok = fabsf(den) > 1e-8f;
        float dens = denok ? den : 1.0f;
        float t = (ddx * dby - ddy * dbx) / dens;
        float u = (ddx * day - ddy * dax) / dens;
        ok = denok && (t >= 0.0f) && (t <= 1.0f) && (u >= 0.0f) && (u <= 1.0f);
        px = ax + t * dax;
        py = ay + t * day;
    } else if (lane < 20) {
        int k = lane - 16;
        px = CA[2 * k]; py = CA[2 * k + 1];
        float rx = px - Bx.x, ry = py - Bx.y;
        float qx = rx * Bx.c + ry * Bx.s;
        float qy = -rx * Bx.s + ry * Bx.c;
        ok = (fabsf(qx) <= Bx.dx * 0.5f + 1e-5f) &&
             (fabsf(qy) <= Bx.dy * 0.5f + 1e-5f);
    } else if (lane < 24) {
        int k = lane - 20;
        px = CB[2 * k]; py = CB[2 * k + 1];
        float rx = px - A.x, ry = py - A.y;
        float qx = rx * A.c + ry * A.s;
        float qy = -rx * A.s + ry * A.c;
        ok = (fabsf(qx) <= A.dx * 0.5f + 1e-5f) &&
             (fabsf(qy) <= A.dy * 0.5f + 1e-5f);
    }
    unsigned mbits = __ballot_sync(FULL, ok) & 0xFFFFFFu;
    int cnt = __popc(mbits);

    float sx = 0.0f, sy = 0.0f;
#pragma unroll
    for (int k = 0; k < 24; k++) {
        float vx = __shfl_sync(FULL, px, k);
        float vy = __shfl_sync(FULL, py, k);
        if ((mbits >> k) & 1u) { sx += vx; sy += vy; }
    }
    float cf = (float)(cnt > 1 ? cnt : 1);
    float cx = sx / cf, cy = sy / cf;

    float ang = ((lane < 24) && ok) ? atan2f(py - cy, px - cx) : 1e9f;

    u64 key;
    if (lane < 24) {
        unsigned u = __float_as_uint(ang);
        unsigned m = (u & 0x80000000u) ? ~u : (u | 0x80000000u);
        key = (((u64)m) << 32) | (unsigned)lane;
    } else {
        key = (((u64)0xFFFFFFFFu) << 32) | (unsigned)lane;
    }

#pragma unroll
    for (unsigned k = 2; k <= 32; k <<= 1) {
#pragma unroll
        for (unsigned jj = k >> 1; jj > 0; jj >>= 1) {
            u64 partner = __shfl_xor_sync(FULL, key, jj);
            bool dirAsc = ((lane & k) == 0);
            bool keepMin = (((lane & jj) == 0) == dirAsc);
            bool take = keepMin ? (partner < key) : (partner > key);
            if (k == 32) {
                take = (((lane & jj) == 0)) ? (partner < key) : (partner > key);
            }
            if (take) key = partner;
        }
    }
    int sidx = (int)(key & 31u);

    float psx = __shfl_sync(FULL, px, sidx);
    float psy = __shfl_sync(FULL, py, sidx);
    bool msk_s = (sidx < 24) && ((mbits >> sidx) & 1u);

    float fx = __shfl_sync(FULL, psx, 0);
    float fy = __shfl_sync(FULL, psy, 0);
    float polx = msk_s ? psx : fx;
    float poly = msk_s ? psy : fy;

    float s2 = 0.0f;
    float curx = __shfl_sync(FULL, polx, 0);
    float cury = __shfl_sync(FULL, poly, 0);
    float firstx = curx, firsty = cury;
#pragma unroll
    for (int k = 0; k < 24; k++) {
        float nxx, nxy;
        if (k == 23) { nxx = firstx; nxy = firsty; }
        else {
            nxx = __shfl_sync(FULL, polx, k + 1);
            nxy = __shfl_sync(FULL, poly, k + 1);
        }
        s2 += curx * nxy - cury * nxx;
        curx = nxx; cury = nxy;
    }
    float inter = 0.5f * fabsf(s2);
    float un = fmaxf(A.area + Bx.area - inter, 1e-6f);
    return inter / un;
}

// ==========================================================================
// 4) pairheavy: ONE WARP PER BOX. Lanes filter the 3x3 neighborhood slab
//    entries in parallel; surviving pairs run warp-collective exact IoU
//    immediately. Also zeroes hist for the next replay.
//    grid = 256 x 256 (2048 warps = BATCH*PRE boxes).
// ==========================================================================
__global__ void pairheavy_kernel() {
    const unsigned FULL = 0xffffffffu;
    int t = blockIdx.x * blockDim.x + threadIdx.x;

    // zero histogram for the next graph replay (hist last read by compact)
    if (t < BATCH * HBINS / 4)
        ((uint4*)g_hist)[t] = make_uint4(0u, 0u, 0u, 0u);

    int w = t >> 5;                 // 0 .. 2047
    int lane = t & 31;
    int b = w >> 10;                // 0..1
    int i = w & (PRE - 1);          // box index (rank)

    float4 fa = g_f4[b][i];
    int bcx = cell_of(fa.x), bcy = cell_of(fa.y);

    for (int n = 0; n < 9; n++) {
        int cx = bcx + (n % 3) - 1;
        int cy = bcy + (n / 3) - 1;
        if (cx < 0 || cx >= NCELLX || cy < 0 || cy >= NCELLX) continue;  // warp-uniform
        int c = cy * NCELLX + cx;
        int cnt = (int)g_cellcnt[b][c];
        if (cnt > CELL_CAP) cnt = CELL_CAP;
        for (int base = 0; base < cnt; base += 32) {
            int p = base + lane;
            int j = -1;
            bool candp = false;
            if (p < cnt) {
                j = g_cellboxes[b][c][p];
                if (j > i) {
                    float4 fb = g_f4[b][j];
                    float amin = fminf(fa.w, fb.w), amax = fmaxf(fa.w, fb.w);
                    if (amin >= 0.795f * amax) {          // iou could exceed thresh
                        float ddx = fa.x - fb.x, ddy = fa.y - fb.y;
                        float rr = fa.z + fb.z + 1e-2f;
                        if (ddx * ddx + ddy * ddy <= rr * rr) candp = true;
                    }
                }
            }
            unsigned mask = __ballot_sync(FULL, candp);
            while (mask) {
                int src = __ffs((int)mask) - 1;
                mask &= mask - 1u;
                int jj = __shfl_sync(FULL, j, src);
                float iou = warp_rotated_iou(b, i, jj, lane);
                if (lane == 0 && iou > NMS_THRESH) {
                    atomicOr(&g_suppby[b][jj][i >> 6], 1ull << (i & 63));  // i suppresses jj (i<jj)
                    atomicOr(&g_rowflag[b][jj >> 6], 1ull << (jj & 63));
                }
            }
        }
    }
}

// ==========================================================================
// 5) Fixpoint greedy NMS + output gather.
// ==========================================================================
__global__ void nms_out_kernel(const float* __restrict__ boxes,
                               const float* __restrict__ cls,
                               float* __restrict__ out, int out_size) {
    __shared__ unsigned kw[32];
    __shared__ int changed;
    int b = blockIdx.x;
    int tid = threadIdx.x;
    int wid = tid >> 5, lane = tid & 31;

    bool flagged = (g_rowflag[b][tid >> 6] >> (tid & 63)) & 1ull;
    u64 sb[NMSW];
#pragma unroll
    for (int w = 0; w < NMSW; w++)
        sb[w] = flagged ? g_suppby[b][tid][w] : 0ull;

    if (tid < 32) kw[tid] = 0xFFFFFFFFu;
    __syncthreads();

    for (int it = 0; it < PRE; it++) {
        u64 sup = 0ull;
        if (flagged) {
#pragma unroll
            for (int w = 0; w < NMSW; w++) {
                u64 Kw = (u64)kw[2 * w] | ((u64)kw[2 * w + 1] << 32);
                sup |= sb[w] & Kw;
            }
        }
        bool kept = (sup == 0ull);
        unsigned bal = __ballot_sync(0xffffffffu, kept);
        __syncthreads();
        if (tid == 0) changed = 0;
        __syncthreads();
        if (lane == 0) {
            if (bal != kw[wid]) { kw[wid] = bal; changed = 1; }
        }
        __syncthreads();
        if (!changed) break;
    }

    int s = tid;
    if (s >= POST) return;
    u64 skeep[NMSW];
#pragma unroll
    for (int w = 0; w < NMSW; w++)
        skeep[w] = (u64)kw[2 * w] | ((u64)kw[2 * w + 1] << 32);

    int pos = -1, c = 0;
#pragma unroll
    for (int w = 0; w < NMSW; w++) {
        u64 kv = skeep[w];
        int pc = __popcll(kv);
        if (pos < 0 && c + pc > s) {
            int r = s - c;
            for (int t = 0; t < r; t++) kv &= kv - 1ull;
            pos = w * 64 + __ffsll((long long)kv) - 1;
        }
        c += pc;
    }
    bool valid = pos >= 0;
    int p = valid ? pos : (PRE - 1);
    int sel = g_topidx[b][p];

    const float* bp = boxes + ((long)b * NBOX + sel) * 7;
    const float* lp = cls + ((long)b * NBOX + sel) * 3;
    float l0 = lp[0], l1 = lp[1], l2 = lp[2];
    float scv = l0; int lab = 0;
    if (l1 > scv) { scv = l1; lab = 1; }
    if (l2 > scv) { scv = l2; lab = 2; }

    const int SC_OFF = BATCH * POST * 7;
    const int LB_OFF = SC_OFF + BATCH * POST;
    const int LG_OFF = LB_OFF + BATCH * POST;
    int base = b * POST + s;

#pragma unroll
    for (int k = 0; k < 7; k++) {
        int o = base * 7 + k;
        if (o < out_size) out[o] = valid ? bp[k] : 0.0f;
    }
    { int o = SC_OFF + base; if (o < out_size) out[o] = valid ? scv : 0.0f; }
    { int o = LB_OFF + base; if (o < out_size) out[o] = valid ? (float)(lab + 1) : 1.0f; }
    {
        float lg[3] = {l0, l1, l2};
#pragma unroll
        for (int k = 0; k < 3; k++) {
            int o = LG_OFF + base * 3 + k;
            if (o < out_size) out[o] = valid ? lg[k] : 0.0f;
        }
    }
}

// ==========================================================================
extern "C" void kernel_launch(void* const* d_in, const int* in_sizes, int n_in,
                              void* d_out, int out_size) {
    const float* boxes = (const float*)d_in[0];  // [2,16384,7]
    const float* cls = (const float*)d_in[1];    // [2,16384,3]
    float* out = (float*)d_out;

    key_kernel<<<(BATCH * NBOX) / 256, 256>>>(cls);
    compact_kernel<<<(BATCH * NBOX) / 256, 256>>>();
    rank_kernel<<<(BATCH * CAND_CAP) / 256, 256>>>(boxes);
    pairheavy_kernel<<<(BATCH * PRE * 32) / 256, 256>>>();
    nms_out_kernel<<<BATCH, TPB>>>(boxes, cls, out, out_size);
}

// round 16
// speedup vs baseline: 1.1789x; 1.1789x over previous
#include <cuda_runtime.h>
#include <stdint.h>

#define BATCH 2
#define NBOX 16384
#define PRE 1024
#define POST 512
#define NMSW 16            // 1024 bits / 64
#define NMS_THRESH 0.8f
#define CAND_CAP 2048
#define PAIR_CAP 32768     // per batch
#define NCELLX 13
#define NCELL (NCELLX * NCELLX)
#define CELL_CAP 64
#define HBITS 14
#define HBINS (1 << HBITS)
#define TPB 1024

typedef unsigned long long u64;

struct __align__(16) Box5 { float x, y, dx, dy, c, s, rad, area; };

__device__ int      g_topidx[BATCH][PRE];
__device__ Box5     g_box[BATCH][PRE];
__device__ float    g_cor[BATCH][PRE][8];
__device__ float4   g_f4[BATCH][PRE];           // x, y, rad, area (by rank)
__device__ u64      g_suppby[BATCH][PRE][NMSW]; // supp_by[j]: bits i<j with iou>th
__device__ u64      g_rowflag[BATCH][NMSW];
__device__ int      g_paircount[BATCH];
__device__ unsigned g_pairs[BATCH][PAIR_CAP];   // i<<10 | j
__device__ u64      g_keys[BATCH][NBOX];
__device__ unsigned g_hist[BATCH][HBINS];       // zeroed in pairfind (cyclic)
__device__ int      g_ccount[BATCH];
__device__ u64      g_cand[BATCH][CAND_CAP];
__device__ unsigned g_cellcnt[BATCH][NCELL];
__device__ int      g_cellboxes[BATCH][NCELL][CELL_CAP];  // 256B-aligned slabs

__device__ __forceinline__ int cell_of(float v) {
    int c = (int)floorf((v + 50.0f) * 0.125f);
    return c < 0 ? 0 : (c > NCELLX - 1 ? NCELLX - 1 : c);
}

// ==========================================================================
// 1) keys + 14-bit-prefix histogram; zeroes all per-replay flags.
//    grid = 128 x 256 = exactly BATCH*NBOX threads.
// ==========================================================================
__global__ void key_kernel(const float* __restrict__ cls) {
    int t = blockIdx.x * blockDim.x + threadIdx.x;
    ((u64*)g_suppby)[t] = 0ull;                  // BATCH*PRE*NMSW == 32768 == #threads
    if (t < BATCH * NMSW) ((u64*)g_rowflag)[t] = 0ull;
    if (t < BATCH) { g_paircount[t] = 0; g_ccount[t] = 0; }
    if (t < BATCH * NCELL) ((unsigned*)g_cellcnt)[t] = 0u;

    int b = t >> 14, i = t & (NBOX - 1);
    const float* p = cls + ((long)t) * 3;
    float sc = fmaxf(p[0], fmaxf(p[1], p[2]));
    unsigned u = __float_as_uint(sc);
    unsigned m = (u & 0x80000000u) ? ~u : (u | 0x80000000u); // ascending monotone
    u64 k = (((u64)(~m)) << 32) | (unsigned)i;  // u64 asc == score desc, idx asc
    g_keys[b][i] = k;
    atomicAdd(&g_hist[b][(unsigned)(k >> (64 - HBITS))], 1u);
}

// ==========================================================================
// 2) compact: per-CTA redundant threshold scan, then compact 256-key slice.
//    grid = 128 x 256.
// ==========================================================================
__global__ void __launch_bounds__(256) compact_kernel() {
    __shared__ unsigned warpsum[8];
    __shared__ unsigned sT;
    int tid = threadIdx.x;
    int t = blockIdx.x * blockDim.x + tid;
    int b = t >> 14, i = t & (NBOX - 1);
    int lane = tid & 31, wid = tid >> 5;

    const unsigned* h = g_hist[b];
    unsigned psum = 0;
    {
        const uint4* h4 = (const uint4*)(h + tid * (HBINS / 256));
#pragma unroll
        for (int k = 0; k < HBINS / 256 / 4; k++) {   // 16 uint4 = 64 bins
            uint4 v = h4[k];
            psum += v.x + v.y + v.z + v.w;
        }
    }
    unsigned sc = psum;
#pragma unroll
    for (int off = 1; off < 32; off <<= 1) {
        unsigned v = __shfl_up_sync(0xffffffffu, sc, off);
        if (lane >= off) sc += v;
    }
    if (lane == 31) warpsum[wid] = sc;
    __syncthreads();
    unsigned woff = 0;
#pragma unroll
    for (int w = 0; w < 8; w++) woff += (w < wid) ? warpsum[w] : 0u;
    unsigned incl = sc + woff;
    unsigned excl = incl - psum;
    if (incl >= PRE && excl < PRE) {
        unsigned c = excl;
        int base = tid * (HBINS / 256);
        for (int k = 0; k < HBINS / 256; k++) {
            c += h[base + k];
            if (c >= PRE) { sT = (unsigned)(base + k); break; }
        }
    }
    __syncthreads();
    unsigned T = sT;

    u64 k = g_keys[b][i];
    if ((unsigned)(k >> (64 - HBITS)) <= T) {
        int pos = atomicAdd(&g_ccount[b], 1);
        if (pos < CAND_CAP) g_cand[b][pos] = k;
    }
}

// ==========================================================================
// 3) rank: stable sorted position = #{keys < mine} (keys unique).
//    Threads with rank < PRE do box prep + direct cell-slab registration.
//    grid = 16 x 256 = BATCH * CAND_CAP threads.
// ==========================================================================
__global__ void __launch_bounds__(256) rank_kernel(const float* __restrict__ boxes) {
    int t = blockIdx.x * blockDim.x + threadIdx.x;
    int b = t / CAND_CAP;
    int c = t - b * CAND_CAP;
    int m = g_ccount[b]; if (m > CAND_CAP) m = CAND_CAP;
    if (c >= m) return;

    const u64* cand = g_cand[b];
    u64 mykey = cand[c];

    int rank = 0;
    int j = 0;
    for (; j + 2 <= m; j += 2) {
        ulonglong2 v = *(const ulonglong2*)(cand + j);
        rank += (v.x < mykey) + (v.y < mykey);
    }
    for (; j < m; j++) rank += (cand[j] < mykey);
    if (rank >= PRE) return;

    int idx = (int)(mykey & 0xFFFFFFFFull);
    g_topidx[b][rank] = idx;
    const float* bp = boxes + ((long)b * NBOX + idx) * 7;
    float x = bp[0], y = bp[1], dx = bp[3], dy = bp[4], r = bp[6];
    float cc = cosf(r), ss = sinf(r);
    Box5 bx;
    bx.x = x; bx.y = y; bx.dx = dx; bx.dy = dy; bx.c = cc; bx.s = ss;
    bx.rad = 0.5f * sqrtf(dx * dx + dy * dy);
    bx.area = dx * dy;
    g_box[b][rank] = bx;
    g_f4[b][rank] = make_float4(x, y, bx.rad, bx.area);
    const float ox[4] = {0.5f, -0.5f, -0.5f, 0.5f};
    const float oy[4] = {0.5f, 0.5f, -0.5f, -0.5f};
    float* co = g_cor[b][rank];
#pragma unroll
    for (int k = 0; k < 4; k++) {
        float lx = dx * ox[k], ly = dy * oy[k];
        co[2 * k]     = x + lx * cc - ly * ss;
        co[2 * k + 1] = y + lx * ss + ly * cc;
    }
    int cell = cell_of(y) * NCELLX + cell_of(x);
    unsigned slot = atomicAdd(&g_cellcnt[b][cell], 1u);
    if (slot < CELL_CAP) g_cellboxes[b][cell][slot] = rank;
}

// ==========================================================================
// 4) pairfind: one thread per (box, neighbor cell), int4 slab reads for MLP.
//    grid = 144 x 128. Also zeroes hist for next replay.
// ==========================================================================
__global__ void __launch_bounds__(128) pairfind_kernel() {
    int t = blockIdx.x * blockDim.x + threadIdx.x;

    // zero histogram for the next graph replay (hist last read by compact)
    for (int z = t; z < BATCH * HBINS / 4; z += 144 * 128)
        ((uint4*)g_hist)[z] = make_uint4(0u, 0u, 0u, 0u);

    if (t >= BATCH * PRE * 9) return;
    int b = t / (PRE * 9);
    int rem = t - b * PRE * 9;
    int i = rem / 9;
    int n = rem - i * 9;

    float4 fa = g_f4[b][i];
    int cx = cell_of(fa.x) + (n % 3) - 1;
    int cy = cell_of(fa.y) + (n / 3) - 1;
    if (cx < 0 || cx >= NCELLX || cy < 0 || cy >= NCELLX) return;
    int c = cy * NCELLX + cx;
    int cnt = (int)g_cellcnt[b][c];
    if (cnt > CELL_CAP) cnt = CELL_CAP;
    const int4* slab4 = (const int4*)g_cellboxes[b][c];   // 256B-aligned

    for (int base = 0; base < cnt; base += 4) {
        int4 v = slab4[base >> 2];          // 4 entries, one load
        int js[4] = {v.x, v.y, v.z, v.w};
        float4 fbs[4];
#pragma unroll
        for (int q = 0; q < 4; q++) {       // 4 independent loads (MLP)
            int j = js[q];
            fbs[q] = (base + q < cnt && j > i) ? g_f4[b][j]
                                               : make_float4(1e9f, 1e9f, 0.f, 0.f);
        }
#pragma unroll
        for (int q = 0; q < 4; q++) {
            if (base + q >= cnt) break;
            int j = js[q];
            if (j <= i) continue;
            float4 fb = fbs[q];
            float amin = fminf(fa.w, fb.w), amax = fmaxf(fa.w, fb.w);
            if (amin < 0.795f * amax) continue;   // iou <= amin/amax < thresh
            float ddx = fa.x - fb.x, ddy = fa.y - fb.y;
            float rr = fa.z + fb.z + 1e-2f;
            if (ddx * ddx + ddy * ddy > rr * rr) continue;
            int pos = atomicAdd(&g_paircount[b], 1);
            if (pos < PAIR_CAP)
                g_pairs[b][pos] = ((unsigned)i << 10) | (unsigned)j;
        }
    }
}

// ==========================================================================
// Warp-parallel reference-faithful rotated BEV IoU (identical to R6-R13)
// ==========================================================================
__device__ __forceinline__ float warp_rotated_iou(int b, int i, int j, int lane) {
    const unsigned FULL = 0xffffffffu;
    Box5 A  = g_box[b][i];
    Box5 Bx = g_box[b][j];
    const float* CA = g_cor[b][i];
    const float* CB = g_cor[b][j];

    float px = 0.0f, py = 0.0f;
    bool ok = false;
    if (lane < 16) {
        int p = lane >> 2, q = lane & 3;
        int p1 = (p + 1) & 3, q1 = (q + 1) & 3;
        float ax = CA[2 * p],  ay = CA[2 * p + 1];
        float dax = CA[2 * p1] - ax, day = CA[2 * p1 + 1] - ay;
        float bx = CB[2 * q],  by = CB[2 * q + 1];
        float dbx = CB[2 * q1] - bx, dby = CB[2 * q1 + 1] - by;
        float den = dax * dby - day * dbx;
        float ddx = bx - ax, ddy = by - ay;
        bool denok = fabsf(den) > 1e-8f;
        float dens = denok ? den : 1.0f;
        float t = (ddx * dby - ddy * dbx) / dens;
        float u = (ddx * day - ddy * dax) / dens;
        ok = denok && (t >= 0.0f) && (t <= 1.0f) && (u >= 0.0f) && (u <= 1.0f);
        px = ax + t * dax;
        py = ay + t * day;
    } else if (lane < 20) {
        int k = lane - 16;
        px = CA[2 * k]; py = CA[2 * k + 1];
        float rx = px - Bx.x, ry = py - Bx.y;
        float qx = rx * Bx.c + ry * Bx.s;
        float qy = -rx * Bx.s + ry * Bx.c;
        ok = (fabsf(qx) <= Bx.dx * 0.5f + 1e-5f) &&
             (fabsf(qy) <= Bx.dy * 0.5f + 1e-5f);
    } else if (lane < 24) {
        int k = lane - 20;
        px = CB[2 * k]; py = CB[2 * k + 1];
        float rx = px - A.x, ry = py - A.y;
        float qx = rx * A.c + ry * A.s;
        float qy = -rx * A.s + ry * A.c;
        ok = (fabsf(qx) <= A.dx * 0.5f + 1e-5f) &&
             (fabsf(qy) <= A.dy * 0.5f + 1e-5f);
    }
    unsigned mbits = __ballot_sync(FULL, ok) & 0xFFFFFFu;
    int cnt = __popc(mbits);

    float sx = 0.0f, sy = 0.0f;
#pragma unroll
    for (int k = 0; k < 24; k++) {
        float vx = __shfl_sync(FULL, px, k);
        float vy = __shfl_sync(FULL, py, k);
        if ((mbits >> k) & 1u) { sx += vx; sy += vy; }
    }
    float cf = (float)(cnt > 1 ? cnt : 1);
    float cx = sx / cf, cy = sy / cf;

    float ang = ((lane < 24) && ok) ? atan2f(py - cy, px - cx) : 1e9f;

    u64 key;
    if (lane < 24) {
        unsigned u = __float_as_uint(ang);
        unsigned m = (u & 0x80000000u) ? ~u : (u | 0x80000000u);
        key = (((u64)m) << 32) | (unsigned)lane;
    } else {
        key = (((u64)0xFFFFFFFFu) << 32) | (unsigned)lane;
    }

#pragma unroll
    for (unsigned k = 2; k <= 32; k <<= 1) {
#pragma unroll
        for (unsigned jj = k >> 1; jj > 0; jj >>= 1) {
            u64 partner = __shfl_xor_sync(FULL, key, jj);
            bool dirAsc = ((lane & k) == 0);
            bool keepMin = (((lane & jj) == 0) == dirAsc);
            bool take = keepMin ? (partner < key) : (partner > key);
            if (k == 32) {
                take = (((lane & jj) == 0)) ? (partner < key) : (partner > key);
            }
            if (take) key = partner;
        }
    }
    int sidx = (int)(key & 31u);

    float psx = __shfl_sync(FULL, px, sidx);
    float psy = __shfl_sync(FULL, py, sidx);
    bool msk_s = (sidx < 24) && ((mbits >> sidx) & 1u);

    float fx = __shfl_sync(FULL, psx, 0);
    float fy = __shfl_sync(FULL, psy, 0);
    float polx = msk_s ? psx : fx;
    float poly = msk_s ? psy : fy;

    float s2 = 0.0f;
    float curx = __shfl_sync(FULL, polx, 0);
    float cury = __shfl_sync(FULL, poly, 0);
    float firstx = curx, firsty = cury;
#pragma unroll
    for (int k = 0; k < 24; k++) {
        float nxx, nxy;
        if (k == 23) { nxx = firstx; nxy = firsty; }
        else {
            nxx = __shfl_sync(FULL, polx, k + 1);
            nxy = __shfl_sync(FULL, poly, k + 1);
        }
        s2 += curx * nxy - cury * nxx;
        curx = nxx; cury = nxy;
    }
    float inter = 0.5f * fabsf(s2);
    float un = fmaxf(A.area + Bx.area - inter, 1e-6f);
    return inter / un;
}

// ==========================================================================
// 5) one warp per pair
// ==========================================================================
__global__ void __launch_bounds__(256) heavy_kernel() {
    int n0 = g_paircount[0]; if (n0 > PAIR_CAP) n0 = PAIR_CAP;
    int n1 = g_paircount[1]; if (n1 > PAIR_CAP) n1 = PAIR_CAP;
    int n = n0 + n1;
    int lane = threadIdx.x & 31;
    int w = (blockIdx.x * blockDim.x + threadIdx.x) >> 5;
    int nw = (gridDim.x * blockDim.x) >> 5;
    for (int t = w; t < n; t += nw) {
        int b = (t >= n0) ? 1 : 0;
        unsigned pk = g_pairs[b][b ? (t - n0) : t];
        int i = (pk >> 10) & 1023;
        int j = pk & 1023;
        float iou = warp_rotated_iou(b, i, j, lane);
        if (lane == 0 && iou > NMS_THRESH) {
            atomicOr(&g_suppby[b][j][i >> 6], 1ull << (i & 63));
            atomicOr(&g_rowflag[b][j >> 6], 1ull << (j & 63));
        }
    }
}

// ==========================================================================
// 6) Fixpoint greedy NMS + output gather.
// ==========================================================================
__global__ void nms_out_kernel(const float* __restrict__ boxes,
                               const float* __restrict__ cls,
                               float* __restrict__ out, int out_size) {
    __shared__ unsigned kw[32];
    __shared__ int changed;
    int b = blockIdx.x;
    int tid = threadIdx.x;
    int wid = tid >> 5, lane = tid & 31;

    bool flagged = (g_rowflag[b][tid >> 6] >> (tid & 63)) & 1ull;
    u64 sb[NMSW];
#pragma unroll
    for (int w = 0; w < NMSW; w++)
        sb[w] = flagged ? g_suppby[b][tid][w] : 0ull;

    if (tid < 32) kw[tid] = 0xFFFFFFFFu;
    __syncthreads();

    for (int it = 0; it < PRE; it++) {
        u64 sup = 0ull;
        if (flagged) {
#pragma unroll
            for (int w = 0; w < NMSW; w++) {
                u64 Kw = (u64)kw[2 * w] | ((u64)kw[2 * w + 1] << 32);
                sup |= sb[w] & Kw;
            }
        }
        bool kept = (sup == 0ull);
        unsigned bal = __ballot_sync(0xffffffffu, kept);
        __syncthreads();
        if (tid == 0) changed = 0;
        __syncthreads();
        if (lane == 0) {
            if (bal != kw[wid]) { kw[wid] = bal; changed = 1; }
        }
        __syncthreads();
        if (!changed) break;
    }

    int s = tid;
    if (s >= POST) return;
    u64 skeep[NMSW];
#pragma unroll
    for (int w = 0; w < NMSW; w++)
        skeep[w] = (u64)kw[2 * w] | ((u64)kw[2 * w + 1] << 32);

    int pos = -1, c = 0;
#pragma unroll
    for (int w = 0; w < NMSW; w++) {
        u64 kv = skeep[w];
        int pc = __popcll(kv);
        if (pos < 0 && c + pc > s) {
            int r = s - c;
            for (int t = 0; t < r; t++) kv &= kv - 1ull;
            pos = w * 64 + __ffsll((long long)kv) - 1;
        }
        c += pc;
    }
    bool valid = pos >= 0;
    int p = valid ? pos : (PRE - 1);
    int sel = g_topidx[b][p];

    const float* bp = boxes + ((long)b * NBOX + sel) * 7;
    const float* lp = cls + ((long)b * NBOX + sel) * 3;
    float l0 = lp[0], l1 = lp[1], l2 = lp[2];
    float scv = l0; int lab = 0;
    if (l1 > scv) { scv = l1; lab = 1; }
    if (l2 > scv) { scv = l2; lab = 2; }

    const int SC_OFF = BATCH * POST * 7;
    const int LB_OFF = SC_OFF + BATCH * POST;
    const int LG_OFF = LB_OFF + BATCH * POST;
    int base = b * POST + s;

#pragma unroll
    for (int k = 0; k < 7; k++) {
        int o = base * 7 + k;
        if (o < out_size) out[o] = valid ? bp[k] : 0.0f;
    }
    { int o = SC_OFF + base; if (o < out_size) out[o] = valid ? scv : 0.0f; }
    { int o = LB_OFF + base; if (o < out_size) out[o] = valid ? (float)(lab + 1) : 1.0f; }
    {
        float lg[3] = {l0, l1, l2};
#pragma unroll
        for (int k = 0; k < 3; k++) {
            int o = LG_OFF + base * 3 + k;
            if (o < out_size) out[o] = valid ? lg[k] : 0.0f;
        }
    }
}

// ==========================================================================
extern "C" void kernel_launch(void* const* d_in, const int* in_sizes, int n_in,
                              void* d_out, int out_size) {
    const float* boxes = (const float*)d_in[0];  // [2,16384,7]
    const float* cls = (const float*)d_in[1];    // [2,16384,3]
    float* out = (float*)d_out;

    key_kernel<<<(BATCH * NBOX) / 256, 256>>>(cls);
    compact_kernel<<<(BATCH * NBOX) / 256, 256>>>();
    rank_kernel<<<(BATCH * CAND_CAP) / 256, 256>>>(boxes);
    pairfind_kernel<<<144, 128>>>();
    heavy_kernel<<<256, 256>>>();
    nms_out_kernel<<<BATCH, TPB>>>(boxes, cls, out, out_size);
}